// round 13
// baseline (speedup 1.0000x reference)
#include <cuda_runtime.h>
#include <math_constants.h>

#define QN 4096
#define VN 2048
#define DN 8192
#define NCHUNK 128   /* row chunks of 32 for the column pass */
#define RPC 32
#define NBANK 64
#define THRESH 2.0f
#define GRP 66       /* blocks per group: 2 col + 32 trip + 32 qdl */

// banks: 0=nce_t2v 1=nce_v2t 2=trip_t2v 3=trip_v2t 4=qdl
// Static zero-init covers run 1; merge's last block resets for graph replays.
__device__ double   g_bank[5][NBANK];
__device__ float    g_colsum[VN];        // col sum of exp(scores_)  (atomic add)
__device__ unsigned g_colkey[VN];        // col max of scores (monotone key, atomic max)
__device__ float    g_rowp[2 * QN];      // row partial sums of exp(scores_)
__device__ float    g_qdlp[2 * VN * 3];  // qdl half-pair partials {xx,yy,xy}
__device__ float    g_trip[QN];          // trip t2v per-row hinge
__device__ float    g_diagS[QN];         // scores [j, j/2]
__device__ float    g_diagS_[QN];        // scores_[j, j/2]
__device__ unsigned g_done;

__device__ __forceinline__ float warpSum(float v) {
    #pragma unroll
    for (int o = 16; o; o >>= 1) v += __shfl_xor_sync(0xffffffffu, v, o);
    return v;
}
__device__ __forceinline__ double warpSumD(double v) {
    #pragma unroll
    for (int o = 16; o; o >>= 1) v += __shfl_xor_sync(0xffffffffu, v, o);
    return v;
}
__device__ __forceinline__ unsigned fkey(float f) {
    unsigned b = __float_as_uint(f);
    return (b & 0x80000000u) ? ~b : (b | 0x80000000u);
}
__device__ __forceinline__ float funkey(unsigned k) {
    return __uint_as_float((k & 0x80000000u) ? (k ^ 0x80000000u) : ~k);
}

// ===========================================================================
// Fused kernel (R9 structure): roles interleaved by row-group so trip rows
// co-run with the col chunk that streams the same scores rows (L2 reuse).
//   idx 0..1   -> col pass (chunk = group, half bx = idx)  [+ diag capture]
//   idx 2..33  -> trip row j = group*32 + idx-2
//   idx 34..65 -> qdl half-pair q = group*32 + idx-34
// ===========================================================================
__global__ void __launch_bounds__(256) k_fused(
        const float* __restrict__ s, const float* __restrict__ s_,
        const float* __restrict__ qhd, const int* __restrict__ rand_idx) {
    int group = blockIdx.x / GRP;
    int idx   = blockIdx.x % GRP;
    int tid = threadIdx.x;
    int w = tid >> 5, l = tid & 31;

    if (idx < 2) {
        // ----------------- column pass -----------------
        int chunk = group, bx = idx;
        int r0 = chunk * RPC;
        int ct = bx * 256 + tid;            // float4 column-tile index (0..511)
        int c0 = ct * 4;
        const float4* P_ = (const float4*)(s_ + (size_t)r0 * VN) + ct;
        const float4* P  = (const float4*)(s  + (size_t)r0 * VN) + ct;
        __shared__ float rowp[8][RPC];
        float4 cs = make_float4(0.f, 0.f, 0.f, 0.f);
        float4 cm = make_float4(-CUDART_INF_F, -CUDART_INF_F, -CUDART_INF_F, -CUDART_INF_F);
        #pragma unroll 8
        for (int r = 0; r < RPC; r++) {
            float4 v_ = __ldcs(&P_[(size_t)r * (VN / 4)]);   // read-once stream
            float4 v  = P [(size_t)r * (VN / 4)];            // keep in L2 for trip role
            float e0 = __expf(v_.x), e1 = __expf(v_.y), e2 = __expf(v_.z), e3 = __expf(v_.w);
            cs.x += e0; cs.y += e1; cs.z += e2; cs.w += e3;
            float rs = warpSum(e0 + e1 + e2 + e3);
            if (l == 0) rowp[w][r] = rs;
            cm.x = fmaxf(cm.x, v.x); cm.y = fmaxf(cm.y, v.y);
            cm.z = fmaxf(cm.z, v.z); cm.w = fmaxf(cm.w, v.w);
        }
        // exclusion fixup + diag capture (4 threads, L1/L2 hits)
        int a0 = chunk * 4;
        if (ct >= a0 && ct < a0 + 4) {
            cm = make_float4(-CUDART_INF_F, -CUDART_INF_F, -CUDART_INF_F, -CUDART_INF_F);
            for (int r = 0; r < RPC; r++) {
                float4 v  = P [(size_t)r * (VN / 4)];
                float4 v_ = P_[(size_t)r * (VN / 4)];
                int row = r0 + r;
                int ex = row >> 1;
                if (ex != c0    ) cm.x = fmaxf(cm.x, v.x); else { g_diagS[row] = v.x; g_diagS_[row] = v_.x; }
                if (ex != c0 + 1) cm.y = fmaxf(cm.y, v.y); else { g_diagS[row] = v.y; g_diagS_[row] = v_.y; }
                if (ex != c0 + 2) cm.z = fmaxf(cm.z, v.z); else { g_diagS[row] = v.z; g_diagS_[row] = v_.z; }
                if (ex != c0 + 3) cm.w = fmaxf(cm.w, v.w); else { g_diagS[row] = v.w; g_diagS_[row] = v_.w; }
            }
        }
        atomicAdd(&g_colsum[c0    ], cs.x);
        atomicAdd(&g_colsum[c0 + 1], cs.y);
        atomicAdd(&g_colsum[c0 + 2], cs.z);
        atomicAdd(&g_colsum[c0 + 3], cs.w);
        atomicMax(&g_colkey[c0    ], fkey(cm.x));
        atomicMax(&g_colkey[c0 + 1], fkey(cm.y));
        atomicMax(&g_colkey[c0 + 2], fkey(cm.z));
        atomicMax(&g_colkey[c0 + 3], fkey(cm.w));
        __syncthreads();
        if (tid < RPC) {
            float t = 0.f;
            #pragma unroll
            for (int i = 0; i < 8; i++) t += rowp[i][tid];
            g_rowp[bx * QN + r0 + tid] = t;
        }
        return;
    }

    if (idx < 34) {
        // ----------------- trip t2v row selection -----------------
        int j = group * RPC + (idx - 2);
        const float* row = s + (size_t)j * VN;
        int lab = j >> 1;                      // labels[j] = j // 2
        const float4* r4 = (const float4*)row;
        float4 a = r4[tid];
        float4 b = r4[tid + 256];
        float x[8] = { a.x, a.y, a.z, a.w, b.x, b.y, b.z, b.w };
        int base0 = tid * 4, base1 = (tid + 256) * 4;
        #pragma unroll
        for (int i = 0; i < 4; i++) {
            if (base0 + i == lab) x[i]     = -CUDART_INF_F;   // positive (999 @ rank 0)
            if (base1 + i == lab) x[4 + i] = -CUDART_INF_F;
        }
        int samp = 1 + rand_idx[j];            // rank among negatives, 1-indexed
        __shared__ float cand[256];
        __shared__ int   cnt;
        if (tid == 0) cnt = 0;
        __syncthreads();
        #pragma unroll
        for (int i = 0; i < 8; i++) {
            if (x[i] > THRESH) {
                int p = atomicAdd(&cnt, 1);
                if (p < 256) cand[p] = x[i];
            }
        }
        __syncthreads();
        int n = cnt;
        if (n >= samp && n <= 256) {
            if (w != 0) return;                // warp 0 finishes alone
            float y[8];
            #pragma unroll
            for (int k = 0; k < 8; k++)
                y[k] = (l + 32 * k < n) ? cand[l + 32 * k] : -CUDART_INF_F;
            float thr = CUDART_INF_F;
            int rank = 1;
            float ans;
            while (true) {
                float m = -CUDART_INF_F;
                #pragma unroll
                for (int k = 0; k < 8; k++) if (y[k] < thr) m = fmaxf(m, y[k]);
                int c = 0;
                #pragma unroll
                for (int k = 0; k < 8; k++) c += (y[k] == m);
                #pragma unroll
                for (int o = 16; o; o >>= 1) {
                    float om = __shfl_xor_sync(0xffffffffu, m, o);
                    int   oc = __shfl_xor_sync(0xffffffffu, c, o);
                    float nm = fmaxf(m, om);
                    c = (m == nm ? c : 0) + (om == nm ? oc : 0);
                    m = nm;
                }
                if (rank + c > samp) { ans = m; break; }
                rank += c;
                thr = m;
            }
            if (l == 0) g_trip[j] = fmaxf(0.f, 0.2f + ans - row[lab]);
            return;
        }
        // ---- fallback: exact block-wide iterative selection (rare) ----
        __shared__ float shf[8];
        __shared__ int   shi[8];
        __shared__ float bm;
        __shared__ int   bc;
        float thr = CUDART_INF_F;
        int rank = 1;
        float ans = 0.f;
        while (true) {
            float m = -CUDART_INF_F;
            #pragma unroll
            for (int i = 0; i < 8; i++) if (x[i] < thr) m = fmaxf(m, x[i]);
            int c = 0;
            #pragma unroll
            for (int i = 0; i < 8; i++) c += (x[i] == m);
            #pragma unroll
            for (int o = 16; o; o >>= 1) {
                float om = __shfl_xor_sync(0xffffffffu, m, o);
                int   oc = __shfl_xor_sync(0xffffffffu, c, o);
                float nm = fmaxf(m, om);
                c = (m == nm ? c : 0) + (om == nm ? oc : 0);
                m = nm;
            }
            if (l == 0) { shf[w] = m; shi[w] = c; }
            __syncthreads();
            if (tid == 0) {
                float M = shf[0]; int C = shi[0];
                #pragma unroll
                for (int i = 1; i < 8; i++) {
                    float nm = fmaxf(M, shf[i]);
                    C = (M == nm ? C : 0) + (shf[i] == nm ? shi[i] : 0);
                    M = nm;
                }
                bm = M; bc = C;
            }
            __syncthreads();
            float m2 = bm; int c2 = bc;
            if (rank + c2 > samp) { ans = m2; break; }
            rank += c2;
            thr = m2;
            __syncthreads();
        }
        if (tid == 0) g_trip[j] = fmaxf(0.f, 0.2f + ans - row[lab]);
        return;
    }

    // ----------------- qdl half-pair partials -----------------
    {
        int q    = group * RPC + (idx - 34);   // 0..4095
        int pair = q >> 1;
        int half = q & 1;
        const float4* A = (const float4*)(qhd + (size_t)(2 * pair)     * DN + half * (DN / 2));
        const float4* B = (const float4*)(qhd + (size_t)(2 * pair + 1) * DN + half * (DN / 2));
        float sxx = 0.f, syy = 0.f, sxy = 0.f;
        #pragma unroll
        for (int i = 0; i < (DN / 8) / 256; i++) {
            int ii = tid + i * 256;
            float4 a = __ldcs(&A[ii]), b = __ldcs(&B[ii]);
            sxx += a.x * a.x + a.y * a.y + a.z * a.z + a.w * a.w;
            syy += b.x * b.x + b.y * b.y + b.z * b.z + b.w * b.w;
            sxy += a.x * b.x + a.y * b.y + a.z * b.z + a.w * b.w;
        }
        sxx = warpSum(sxx); syy = warpSum(syy); sxy = warpSum(sxy);
        __shared__ float sh[3][8];
        if (l == 0) { sh[0][w] = sxx; sh[1][w] = syy; sh[2][w] = sxy; }
        __syncthreads();
        if (tid == 0) {
            float X = 0.f, Y = 0.f, Z = 0.f;
            #pragma unroll
            for (int i = 0; i < 8; i++) { X += sh[0][i]; Y += sh[1][i]; Z += sh[2][i]; }
            float* dst = &g_qdlp[(size_t)q * 3];
            dst[0] = X; dst[1] = Y; dst[2] = Z;
        }
    }
}

// ===========================================================================
// Merge + final + reset. 64 blocks x 128 (one work item per thread), __logf.
//   gid <  4096        : NCE t2v row + trip t2v pickup
//   4096 <= gid < 6144 : per-video column finalization (NCE v2t + trip v2t)
//   6144 <= gid < 8192 : QDL pair finalization
// ===========================================================================
__global__ void __launch_bounds__(128) k_merge(float* __restrict__ out) {
    int gid = blockIdx.x * 128 + threadIdx.x;
    int tid = threadIdx.x;
    int w = tid >> 5, l = tid & 31;
    if (gid < QN) {
        int j = gid;
        float nce_val = __logf(g_rowp[j] + g_rowp[QN + j]) - g_diagS_[j];
        float trip_val = g_trip[j];
        nce_val  = warpSum(nce_val);
        trip_val = warpSum(trip_val);
        if (l == 0) {
            atomicAdd(&g_bank[0][(j >> 5) & (NBANK - 1)], (double)nce_val);
            atomicAdd(&g_bank[2][(j >> 5) & (NBANK - 1)], (double)trip_val);
        }
    } else if (gid < QN + VN) {
        int v = gid - QN;
        float cs = g_colsum[v];
        float cm = funkey(g_colkey[v]);
        float a = g_diagS_[2 * v], b = g_diagS_[2 * v + 1];
        float nce_val = __logf(cs) - __logf(__expf(a) + __expf(b));
        float ta = g_diagS[2 * v], tb = g_diagS[2 * v + 1];
        float trip_val = fmaxf(0.f, 0.2f + cm - 0.5f * (ta + tb));
        nce_val  = warpSum(nce_val);
        trip_val = warpSum(trip_val);
        if (l == 0) {
            atomicAdd(&g_bank[1][(v >> 5) & (NBANK - 1)], (double)nce_val);
            atomicAdd(&g_bank[3][(v >> 5) & (NBANK - 1)], (double)trip_val);
        }
    } else {
        int p = gid - QN - VN;
        const float* h0 = &g_qdlp[(size_t)(2 * p) * 3];
        const float* h1 = &g_qdlp[(size_t)(2 * p + 1) * 3];
        float X = h0[0] + h1[0], Y = h0[1] + h1[1], Z = h0[2] + h1[2];
        float nx = fmaxf(sqrtf(X), 1e-12f);
        float ny = fmaxf(sqrtf(Y), 1e-12f);
        float c  = Z / (nx * ny);
        float z  = 32.0f * (c + 0.1f);
        float sp = (z > 20.0f) ? z : log1pf(__expf(z));
        sp = warpSum(2.0f * sp);
        if (l == 0) atomicAdd(&g_bank[4][(p >> 5) & (NBANK - 1)], (double)sp);
    }

    // ---- last-block final combine + reset ----
    __threadfence();
    __shared__ int lastb;
    __syncthreads();
    if (tid == 0) lastb = (atomicAdd(&g_done, 1u) == gridDim.x - 1);
    __syncthreads();
    if (!lastb) return;
    __threadfence();

    // 4 warps cover the 5 banks (warp 0 takes banks 0 and 4)
    __shared__ double bsum[5];
    for (int b = w; b < 5; b += 4) {
        double v = g_bank[b][l] + g_bank[b][l + 32];
        v = warpSumD(v);
        if (l == 0) bsum[b] = v;
    }
    __syncthreads();
    if (tid == 0) {
        double total = 0.02 * (bsum[0] / QN + bsum[1] / VN)
                     + (bsum[2] / QN + bsum[3] / VN)
                     + 0.04 * (bsum[4] / QN);
        out[0] = (float)total;
    }
    __syncthreads();   // read-out strictly before reset
    for (int i = tid; i < 5 * NBANK; i += 128) ((double*)g_bank)[i] = 0.0;
    for (int i = tid; i < VN; i += 128) { g_colsum[i] = 0.f; g_colkey[i] = 0u; }
    if (tid == 0) g_done = 0u;
}

extern "C" void kernel_launch(void* const* d_in, const int* in_sizes, int n_in,
                              void* d_out, int out_size) {
    const float* scores   = (const float*)d_in[0];   // hd_similarity_scores  [Q,V]
    const float* scores_  = (const float*)d_in[1];   // hd_similarity_scores_ [Q,V]
    const float* qhd      = (const float*)d_in[2];   // query_hd [Q,D]
    const int*   rand_idx = (const int*)d_in[4];
    float* out = (float*)d_out;

    k_fused<<<NCHUNK * GRP, 256>>>(scores, scores_, qhd, rand_idx);
    k_merge<<<(QN + 2 * VN) / 128, 128>>>(out);
}

// round 15
// speedup vs baseline: 1.2641x; 1.2641x over previous
#include <cuda_runtime.h>
#include <math_constants.h>

#define QN 4096
#define VN 2048
#define DN 8192
#define NCHUNK 128   /* row chunks of 32 for the column pass */
#define RPC 32
#define NBANK 64
#define THRESH 2.0f
#define GRP 66       /* blocks per group: 2 col + 32 trip + 32 qdl */

// banks: 0=nce_t2v 1=nce_v2t 2=trip_t2v 3=trip_v2t 4=qdl
// Static zero-init covers run 1; merge's last block resets for graph replays.
__device__ double   g_bank[5][NBANK];
__device__ float    g_colsum[VN];        // col sum of exp(scores_)  (atomic add)
__device__ unsigned g_colkey[VN];        // col max of scores (monotone key, atomic max)
__device__ float    g_nceRow[QN];        // per-row NCE t2v value (computed by trip role)
__device__ float    g_qdlp[2 * VN * 3];  // qdl half-pair partials {xx,yy,xy}
__device__ float    g_trip[QN];          // trip t2v per-row hinge
__device__ float    g_diagS[QN];         // scores [j, j/2]
__device__ float    g_diagS_[QN];        // scores_[j, j/2]
__device__ unsigned g_done;

__device__ __forceinline__ float warpSum(float v) {
    #pragma unroll
    for (int o = 16; o; o >>= 1) v += __shfl_xor_sync(0xffffffffu, v, o);
    return v;
}
__device__ __forceinline__ double warpSumD(double v) {
    #pragma unroll
    for (int o = 16; o; o >>= 1) v += __shfl_xor_sync(0xffffffffu, v, o);
    return v;
}
__device__ __forceinline__ unsigned fkey(float f) {
    unsigned b = __float_as_uint(f);
    return (b & 0x80000000u) ? ~b : (b | 0x80000000u);
}
__device__ __forceinline__ float funkey(unsigned k) {
    return __uint_as_float((k & 0x80000000u) ? (k ^ 0x80000000u) : ~k);
}

// ===========================================================================
// Fused kernel: roles interleaved by row-group so trip rows co-run with the
// col chunk that streams the same scores rows (L2 reuse).
//   idx 0..1   -> col pass (chunk = group, half bx = idx)  [+ diag capture]
//                 (pure stream now: row sums moved to the trip role)
//   idx 2..33  -> trip row j = group*32 + idx-2  [+ NCE t2v row value]
//   idx 34..65 -> qdl half-pair q = group*32 + idx-34
// ===========================================================================
__global__ void __launch_bounds__(256) k_fused(
        const float* __restrict__ s, const float* __restrict__ s_,
        const float* __restrict__ qhd, const int* __restrict__ rand_idx) {
    int group = blockIdx.x / GRP;
    int idx   = blockIdx.x % GRP;
    int tid = threadIdx.x;
    int w = tid >> 5, l = tid & 31;

    if (idx < 2) {
        // ----------------- column pass (pure streaming) -----------------
        int chunk = group, bx = idx;
        int r0 = chunk * RPC;
        int ct = bx * 256 + tid;            // float4 column-tile index (0..511)
        int c0 = ct * 4;
        const float4* P_ = (const float4*)(s_ + (size_t)r0 * VN) + ct;
        const float4* P  = (const float4*)(s  + (size_t)r0 * VN) + ct;
        float4 cs = make_float4(0.f, 0.f, 0.f, 0.f);
        float4 cm = make_float4(-CUDART_INF_F, -CUDART_INF_F, -CUDART_INF_F, -CUDART_INF_F);
        #pragma unroll 4
        for (int r = 0; r < RPC; r++) {
            float4 v_ = P_[(size_t)r * (VN / 4)];   // read twice (trip role too) -> default policy
            float4 v  = P [(size_t)r * (VN / 4)];   // keep in L2 for trip role
            cs.x += __expf(v_.x); cs.y += __expf(v_.y);
            cs.z += __expf(v_.z); cs.w += __expf(v_.w);
            cm.x = fmaxf(cm.x, v.x); cm.y = fmaxf(cm.y, v.y);
            cm.z = fmaxf(cm.z, v.z); cm.w = fmaxf(cm.w, v.w);
        }
        // exclusion fixup + diag capture (4 threads, L1/L2 hits)
        int a0 = chunk * 4;
        if (ct >= a0 && ct < a0 + 4) {
            cm = make_float4(-CUDART_INF_F, -CUDART_INF_F, -CUDART_INF_F, -CUDART_INF_F);
            for (int r = 0; r < RPC; r++) {
                float4 v  = P [(size_t)r * (VN / 4)];
                float4 v_ = P_[(size_t)r * (VN / 4)];
                int row = r0 + r;
                int ex = row >> 1;
                if (ex != c0    ) cm.x = fmaxf(cm.x, v.x); else { g_diagS[row] = v.x; g_diagS_[row] = v_.x; }
                if (ex != c0 + 1) cm.y = fmaxf(cm.y, v.y); else { g_diagS[row] = v.y; g_diagS_[row] = v_.y; }
                if (ex != c0 + 2) cm.z = fmaxf(cm.z, v.z); else { g_diagS[row] = v.z; g_diagS_[row] = v_.z; }
                if (ex != c0 + 3) cm.w = fmaxf(cm.w, v.w); else { g_diagS[row] = v.w; g_diagS_[row] = v_.w; }
            }
        }
        atomicAdd(&g_colsum[c0    ], cs.x);
        atomicAdd(&g_colsum[c0 + 1], cs.y);
        atomicAdd(&g_colsum[c0 + 2], cs.z);
        atomicAdd(&g_colsum[c0 + 3], cs.w);
        atomicMax(&g_colkey[c0    ], fkey(cm.x));
        atomicMax(&g_colkey[c0 + 1], fkey(cm.y));
        atomicMax(&g_colkey[c0 + 2], fkey(cm.z));
        atomicMax(&g_colkey[c0 + 3], fkey(cm.w));
        return;
    }

    if (idx < 34) {
        // ------- trip t2v row selection + NCE t2v row value -------
        int j = group * RPC + (idx - 2);
        const float* row  = s  + (size_t)j * VN;
        const float* row_ = s_ + (size_t)j * VN;
        int lab = j >> 1;                      // labels[j] = j // 2
        const float4* r4  = (const float4*)row;
        const float4* r4_ = (const float4*)row_;
        float4 a = r4[tid];
        float4 b = r4[tid + 256];
        float x[8] = { a.x, a.y, a.z, a.w, b.x, b.y, b.z, b.w };
        // row exp-sum for NCE t2v (absorbed into this block's latency slack)
        float4 a_ = r4_[tid];
        float4 b_ = r4_[tid + 256];
        float esum = __expf(a_.x) + __expf(a_.y) + __expf(a_.z) + __expf(a_.w)
                   + __expf(b_.x) + __expf(b_.y) + __expf(b_.z) + __expf(b_.w);
        esum = warpSum(esum);
        __shared__ float rsum_sh[8];
        if (l == 0) rsum_sh[w] = esum;
        int base0 = tid * 4, base1 = (tid + 256) * 4;
        #pragma unroll
        for (int i = 0; i < 4; i++) {
            if (base0 + i == lab) x[i]     = -CUDART_INF_F;   // positive (999 @ rank 0)
            if (base1 + i == lab) x[4 + i] = -CUDART_INF_F;
        }
        int samp = 1 + rand_idx[j];            // rank among negatives, 1-indexed
        __shared__ float cand[256];
        __shared__ int   cnt;
        if (tid == 0) cnt = 0;
        __syncthreads();
        if (tid == 0) {
            float rs = 0.f;
            #pragma unroll
            for (int i = 0; i < 8; i++) rs += rsum_sh[i];
            g_nceRow[j] = __logf(rs) - row_[lab];
        }
        #pragma unroll
        for (int i = 0; i < 8; i++) {
            if (x[i] > THRESH) {
                int p = atomicAdd(&cnt, 1);
                if (p < 256) cand[p] = x[i];
            }
        }
        __syncthreads();
        int n = cnt;
        if (n >= samp && n <= 256) {
            if (w != 0) return;                // warp 0 finishes alone
            float y[8];
            #pragma unroll
            for (int k = 0; k < 8; k++)
                y[k] = (l + 32 * k < n) ? cand[l + 32 * k] : -CUDART_INF_F;
            float thr = CUDART_INF_F;
            int rank = 1;
            float ans;
            while (true) {
                float m = -CUDART_INF_F;
                #pragma unroll
                for (int k = 0; k < 8; k++) if (y[k] < thr) m = fmaxf(m, y[k]);
                int c = 0;
                #pragma unroll
                for (int k = 0; k < 8; k++) c += (y[k] == m);
                #pragma unroll
                for (int o = 16; o; o >>= 1) {
                    float om = __shfl_xor_sync(0xffffffffu, m, o);
                    int   oc = __shfl_xor_sync(0xffffffffu, c, o);
                    float nm = fmaxf(m, om);
                    c = (m == nm ? c : 0) + (om == nm ? oc : 0);
                    m = nm;
                }
                if (rank + c > samp) { ans = m; break; }
                rank += c;
                thr = m;
            }
            if (l == 0) g_trip[j] = fmaxf(0.f, 0.2f + ans - row[lab]);
            return;
        }
        // ---- fallback: exact block-wide iterative selection (rare) ----
        __shared__ float shf[8];
        __shared__ int   shi[8];
        __shared__ float bm;
        __shared__ int   bc;
        float thr = CUDART_INF_F;
        int rank = 1;
        float ans = 0.f;
        while (true) {
            float m = -CUDART_INF_F;
            #pragma unroll
            for (int i = 0; i < 8; i++) if (x[i] < thr) m = fmaxf(m, x[i]);
            int c = 0;
            #pragma unroll
            for (int i = 0; i < 8; i++) c += (x[i] == m);
            #pragma unroll
            for (int o = 16; o; o >>= 1) {
                float om = __shfl_xor_sync(0xffffffffu, m, o);
                int   oc = __shfl_xor_sync(0xffffffffu, c, o);
                float nm = fmaxf(m, om);
                c = (m == nm ? c : 0) + (om == nm ? oc : 0);
                m = nm;
            }
            if (l == 0) { shf[w] = m; shi[w] = c; }
            __syncthreads();
            if (tid == 0) {
                float M = shf[0]; int C = shi[0];
                #pragma unroll
                for (int i = 1; i < 8; i++) {
                    float nm = fmaxf(M, shf[i]);
                    C = (M == nm ? C : 0) + (shf[i] == nm ? shi[i] : 0);
                    M = nm;
                }
                bm = M; bc = C;
            }
            __syncthreads();
            float m2 = bm; int c2 = bc;
            if (rank + c2 > samp) { ans = m2; break; }
            rank += c2;
            thr = m2;
            __syncthreads();
        }
        if (tid == 0) g_trip[j] = fmaxf(0.f, 0.2f + ans - row[lab]);
        return;
    }

    // ----------------- qdl half-pair partials -----------------
    {
        int q    = group * RPC + (idx - 34);   // 0..4095
        int pair = q >> 1;
        int half = q & 1;
        const float4* A = (const float4*)(qhd + (size_t)(2 * pair)     * DN + half * (DN / 2));
        const float4* B = (const float4*)(qhd + (size_t)(2 * pair + 1) * DN + half * (DN / 2));
        float sxx = 0.f, syy = 0.f, sxy = 0.f;
        #pragma unroll
        for (int i = 0; i < (DN / 8) / 256; i++) {
            int ii = tid + i * 256;
            float4 a = __ldcs(&A[ii]), b = __ldcs(&B[ii]);
            sxx += a.x * a.x + a.y * a.y + a.z * a.z + a.w * a.w;
            syy += b.x * b.x + b.y * b.y + b.z * b.z + b.w * b.w;
            sxy += a.x * b.x + a.y * b.y + a.z * b.z + a.w * b.w;
        }
        sxx = warpSum(sxx); syy = warpSum(syy); sxy = warpSum(sxy);
        __shared__ float sh[3][8];
        if (l == 0) { sh[0][w] = sxx; sh[1][w] = syy; sh[2][w] = sxy; }
        __syncthreads();
        if (tid == 0) {
            float X = 0.f, Y = 0.f, Z = 0.f;
            #pragma unroll
            for (int i = 0; i < 8; i++) { X += sh[0][i]; Y += sh[1][i]; Z += sh[2][i]; }
            float* dst = &g_qdlp[(size_t)q * 3];
            dst[0] = X; dst[1] = Y; dst[2] = Z;
        }
    }
}

// ===========================================================================
// Merge + final + reset. 32 blocks x 256. All reads dense & coalesced.
//   gid <  4096        : NCE t2v row + trip t2v pickup (pure loads)
//   4096 <= gid < 6144 : per-video column finalization (NCE v2t + trip v2t)
//   6144 <= gid < 8192 : QDL pair finalization
// ===========================================================================
__global__ void k_merge(float* __restrict__ out) {
    int gid = blockIdx.x * 256 + threadIdx.x;
    int l = threadIdx.x & 31;
    if (gid < QN) {
        int j = gid;
        float nce_val  = g_nceRow[j];
        float trip_val = g_trip[j];
        nce_val  = warpSum(nce_val);
        trip_val = warpSum(trip_val);
        if (l == 0) {
            atomicAdd(&g_bank[0][(j >> 5) & (NBANK - 1)], (double)nce_val);
            atomicAdd(&g_bank[2][(j >> 5) & (NBANK - 1)], (double)trip_val);
        }
    } else if (gid < QN + VN) {
        int v = gid - QN;
        float cs = g_colsum[v];
        float cm = funkey(g_colkey[v]);
        float a = g_diagS_[2 * v], b = g_diagS_[2 * v + 1];
        float nce_val = __logf(cs) - __logf(__expf(a) + __expf(b));
        float ta = g_diagS[2 * v], tb = g_diagS[2 * v + 1];
        float trip_val = fmaxf(0.f, 0.2f + cm - 0.5f * (ta + tb));
        nce_val  = warpSum(nce_val);
        trip_val = warpSum(trip_val);
        if (l == 0) {
            atomicAdd(&g_bank[1][(v >> 5) & (NBANK - 1)], (double)nce_val);
            atomicAdd(&g_bank[3][(v >> 5) & (NBANK - 1)], (double)trip_val);
        }
    } else if (gid < QN + 2 * VN) {
        int p = gid - QN - VN;
        const float* h0 = &g_qdlp[(size_t)(2 * p) * 3];
        const float* h1 = &g_qdlp[(size_t)(2 * p + 1) * 3];
        float X = h0[0] + h1[0], Y = h0[1] + h1[1], Z = h0[2] + h1[2];
        float nx = fmaxf(sqrtf(X), 1e-12f);
        float ny = fmaxf(sqrtf(Y), 1e-12f);
        float c  = Z / (nx * ny);
        float z  = 32.0f * (c + 0.1f);
        float sp = (z > 20.0f) ? z : log1pf(__expf(z));
        sp = warpSum(2.0f * sp);
        if (l == 0) atomicAdd(&g_bank[4][(p >> 5) & (NBANK - 1)], (double)sp);
    }

    // ---- last-block final combine + reset ----
    __threadfence();
    __shared__ int lastb;
    __syncthreads();
    if (threadIdx.x == 0) lastb = (atomicAdd(&g_done, 1u) == gridDim.x - 1);
    __syncthreads();
    if (!lastb) return;
    __threadfence();

    __shared__ double bsum[5];
    int wp = threadIdx.x >> 5;
    if (wp < 5) {
        double v = g_bank[wp][l] + g_bank[wp][l + 32];
        v = warpSumD(v);
        if (l == 0) bsum[wp] = v;
    }
    __syncthreads();
    if (threadIdx.x == 0) {
        double total = 0.02 * (bsum[0] / QN + bsum[1] / VN)
                     + (bsum[2] / QN + bsum[3] / VN)
                     + 0.04 * (bsum[4] / QN);
        out[0] = (float)total;
    }
    __syncthreads();   // read-out strictly before reset
    for (int i = threadIdx.x; i < 5 * NBANK; i += 256) ((double*)g_bank)[i] = 0.0;
    for (int i = threadIdx.x; i < VN; i += 256) { g_colsum[i] = 0.f; g_colkey[i] = 0u; }
    if (threadIdx.x == 0) g_done = 0u;
}

extern "C" void kernel_launch(void* const* d_in, const int* in_sizes, int n_in,
                              void* d_out, int out_size) {
    const float* scores   = (const float*)d_in[0];   // hd_similarity_scores  [Q,V]
    const float* scores_  = (const float*)d_in[1];   // hd_similarity_scores_ [Q,V]
    const float* qhd      = (const float*)d_in[2];   // query_hd [Q,D]
    const int*   rand_idx = (const int*)d_in[4];
    float* out = (float*)d_out;

    k_fused<<<NCHUNK * GRP, 256>>>(scores, scores_, qhd, rand_idx);
    k_merge<<<(QN + 2 * VN) / 256, 256>>>(out);
}

// round 16
// speedup vs baseline: 1.3150x; 1.0402x over previous
#include <cuda_runtime.h>
#include <math_constants.h>

#define QN 4096
#define VN 2048
#define DN 8192
#define NCHUNK 128   /* row chunks of 32 */
#define RPC 32
#define NBANK 64
#define THRESH 2.0f
#define GRP 68       /* blocks per group: 4 col + 32 trip + 32 qdl */

// banks: 0=nce_t2v 1=nce_v2t 2=trip_t2v 3=trip_v2t 4=qdl
// Static zero-init covers run 1; merge's last block resets for graph replays.
__device__ double   g_bank[5][NBANK];
__device__ float    g_colsum[VN];        // col sum of exp(scores_)  (atomic add)
__device__ unsigned g_colkey[VN];        // col max of scores (monotone key, atomic max)
__device__ float    g_nceRow[QN];        // per-row NCE t2v value (computed by trip role)
__device__ float    g_qdlp[2 * VN * 3];  // qdl half-pair partials {xx,yy,xy}
__device__ float    g_trip[QN];          // trip t2v per-row hinge
__device__ float    g_diagS[QN];         // scores [j, j/2]
__device__ float    g_diagS_[QN];        // scores_[j, j/2]
__device__ unsigned g_done;

__device__ __forceinline__ float warpSum(float v) {
    #pragma unroll
    for (int o = 16; o; o >>= 1) v += __shfl_xor_sync(0xffffffffu, v, o);
    return v;
}
__device__ __forceinline__ double warpSumD(double v) {
    #pragma unroll
    for (int o = 16; o; o >>= 1) v += __shfl_xor_sync(0xffffffffu, v, o);
    return v;
}
__device__ __forceinline__ unsigned fkey(float f) {
    unsigned b = __float_as_uint(f);
    return (b & 0x80000000u) ? ~b : (b | 0x80000000u);
}
__device__ __forceinline__ float funkey(unsigned k) {
    return __uint_as_float((k & 0x80000000u) ? (k ^ 0x80000000u) : ~k);
}

// ===========================================================================
// Fused kernel: roles interleaved by row-group so trip rows co-run with the
// col blocks that stream the same scores rows (L2 reuse).
//   idx 0..3   -> col pass quarter: bx = idx&1 (col half), rh = idx>>1 (row
//                 half); 16 rows x 1024 cols = 128 KB per block  [+ diag]
//   idx 4..35  -> trip row j = group*32 + idx-4  [+ NCE t2v row value]
//   idx 36..67 -> qdl half-pair q = group*32 + idx-36
// ===========================================================================
__global__ void __launch_bounds__(256) k_fused(
        const float* __restrict__ s, const float* __restrict__ s_,
        const float* __restrict__ qhd, const int* __restrict__ rand_idx) {
    int group = blockIdx.x / GRP;
    int idx   = blockIdx.x % GRP;
    int tid = threadIdx.x;
    int w = tid >> 5, l = tid & 31;

    if (idx < 4) {
        // ----------------- column pass quarter (pure streaming) -----------------
        int chunk = group;
        int bx = idx & 1;                   // column half
        int rh = idx >> 1;                  // row half
        int r0 = chunk * RPC + rh * 16;
        int ct = bx * 256 + tid;            // float4 column-tile index (0..511)
        int c0 = ct * 4;
        const float4* P_ = (const float4*)(s_ + (size_t)r0 * VN) + ct;
        const float4* P  = (const float4*)(s  + (size_t)r0 * VN) + ct;
        float4 cs = make_float4(0.f, 0.f, 0.f, 0.f);
        float4 cm = make_float4(-CUDART_INF_F, -CUDART_INF_F, -CUDART_INF_F, -CUDART_INF_F);
        #pragma unroll 4
        for (int r = 0; r < 16; r++) {
            float4 v_ = P_[(size_t)r * (VN / 4)];   // read twice (trip role too)
            float4 v  = P [(size_t)r * (VN / 4)];   // keep in L2 for trip role
            cs.x += __expf(v_.x); cs.y += __expf(v_.y);
            cs.z += __expf(v_.z); cs.w += __expf(v_.w);
            cm.x = fmaxf(cm.x, v.x); cm.y = fmaxf(cm.y, v.y);
            cm.z = fmaxf(cm.z, v.z); cm.w = fmaxf(cm.w, v.w);
        }
        // exclusion fixup + diag capture: affected float4 tiles for this
        // 16-row span are [chunk*4 + rh*2, +2); each owned column's 2 group
        // rows lie inside this block's row range. (2 threads redo 16 rows.)
        int a0 = chunk * 4 + rh * 2;
        if (ct >= a0 && ct < a0 + 2) {
            cm = make_float4(-CUDART_INF_F, -CUDART_INF_F, -CUDART_INF_F, -CUDART_INF_F);
            for (int r = 0; r < 16; r++) {
                float4 v  = P [(size_t)r * (VN / 4)];
                float4 v_ = P_[(size_t)r * (VN / 4)];
                int row = r0 + r;
                int ex = row >> 1;
                if (ex != c0    ) cm.x = fmaxf(cm.x, v.x); else { g_diagS[row] = v.x; g_diagS_[row] = v_.x; }
                if (ex != c0 + 1) cm.y = fmaxf(cm.y, v.y); else { g_diagS[row] = v.y; g_diagS_[row] = v_.y; }
                if (ex != c0 + 2) cm.z = fmaxf(cm.z, v.z); else { g_diagS[row] = v.z; g_diagS_[row] = v_.z; }
                if (ex != c0 + 3) cm.w = fmaxf(cm.w, v.w); else { g_diagS[row] = v.w; g_diagS_[row] = v_.w; }
            }
        }
        atomicAdd(&g_colsum[c0    ], cs.x);
        atomicAdd(&g_colsum[c0 + 1], cs.y);
        atomicAdd(&g_colsum[c0 + 2], cs.z);
        atomicAdd(&g_colsum[c0 + 3], cs.w);
        atomicMax(&g_colkey[c0    ], fkey(cm.x));
        atomicMax(&g_colkey[c0 + 1], fkey(cm.y));
        atomicMax(&g_colkey[c0 + 2], fkey(cm.z));
        atomicMax(&g_colkey[c0 + 3], fkey(cm.w));
        return;
    }

    if (idx < 36) {
        // ------- trip t2v row selection + NCE t2v row value -------
        int j = group * RPC + (idx - 4);
        const float* row  = s  + (size_t)j * VN;
        const float* row_ = s_ + (size_t)j * VN;
        int lab = j >> 1;                      // labels[j] = j // 2
        const float4* r4  = (const float4*)row;
        const float4* r4_ = (const float4*)row_;
        float4 a = r4[tid];
        float4 b = r4[tid + 256];
        float x[8] = { a.x, a.y, a.z, a.w, b.x, b.y, b.z, b.w };
        // row exp-sum for NCE t2v (absorbed into this block's latency slack)
        float4 a_ = r4_[tid];
        float4 b_ = r4_[tid + 256];
        float esum = __expf(a_.x) + __expf(a_.y) + __expf(a_.z) + __expf(a_.w)
                   + __expf(b_.x) + __expf(b_.y) + __expf(b_.z) + __expf(b_.w);
        esum = warpSum(esum);
        __shared__ float rsum_sh[8];
        if (l == 0) rsum_sh[w] = esum;
        int base0 = tid * 4, base1 = (tid + 256) * 4;
        #pragma unroll
        for (int i = 0; i < 4; i++) {
            if (base0 + i == lab) x[i]     = -CUDART_INF_F;   // positive (999 @ rank 0)
            if (base1 + i == lab) x[4 + i] = -CUDART_INF_F;
        }
        int samp = 1 + rand_idx[j];            // rank among negatives, 1-indexed
        __shared__ float cand[256];
        __shared__ int   cnt;
        if (tid == 0) cnt = 0;
        __syncthreads();
        if (tid == 0) {
            float rs = 0.f;
            #pragma unroll
            for (int i = 0; i < 8; i++) rs += rsum_sh[i];
            g_nceRow[j] = __logf(rs) - row_[lab];
        }
        #pragma unroll
        for (int i = 0; i < 8; i++) {
            if (x[i] > THRESH) {
                int p = atomicAdd(&cnt, 1);
                if (p < 256) cand[p] = x[i];
            }
        }
        __syncthreads();
        int n = cnt;
        if (n >= samp && n <= 256) {
            if (w != 0) return;                // warp 0 finishes alone
            float y[8];
            #pragma unroll
            for (int k = 0; k < 8; k++)
                y[k] = (l + 32 * k < n) ? cand[l + 32 * k] : -CUDART_INF_F;
            float thr = CUDART_INF_F;
            int rank = 1;
            float ans;
            while (true) {
                float m = -CUDART_INF_F;
                #pragma unroll
                for (int k = 0; k < 8; k++) if (y[k] < thr) m = fmaxf(m, y[k]);
                int c = 0;
                #pragma unroll
                for (int k = 0; k < 8; k++) c += (y[k] == m);
                #pragma unroll
                for (int o = 16; o; o >>= 1) {
                    float om = __shfl_xor_sync(0xffffffffu, m, o);
                    int   oc = __shfl_xor_sync(0xffffffffu, c, o);
                    float nm = fmaxf(m, om);
                    c = (m == nm ? c : 0) + (om == nm ? oc : 0);
                    m = nm;
                }
                if (rank + c > samp) { ans = m; break; }
                rank += c;
                thr = m;
            }
            if (l == 0) g_trip[j] = fmaxf(0.f, 0.2f + ans - row[lab]);
            return;
        }
        // ---- fallback: exact block-wide iterative selection (rare) ----
        __shared__ float shf[8];
        __shared__ int   shi[8];
        __shared__ float bm;
        __shared__ int   bc;
        float thr = CUDART_INF_F;
        int rank = 1;
        float ans = 0.f;
        while (true) {
            float m = -CUDART_INF_F;
            #pragma unroll
            for (int i = 0; i < 8; i++) if (x[i] < thr) m = fmaxf(m, x[i]);
            int c = 0;
            #pragma unroll
            for (int i = 0; i < 8; i++) c += (x[i] == m);
            #pragma unroll
            for (int o = 16; o; o >>= 1) {
                float om = __shfl_xor_sync(0xffffffffu, m, o);
                int   oc = __shfl_xor_sync(0xffffffffu, c, o);
                float nm = fmaxf(m, om);
                c = (m == nm ? c : 0) + (om == nm ? oc : 0);
                m = nm;
            }
            if (l == 0) { shf[w] = m; shi[w] = c; }
            __syncthreads();
            if (tid == 0) {
                float M = shf[0]; int C = shi[0];
                #pragma unroll
                for (int i = 1; i < 8; i++) {
                    float nm = fmaxf(M, shf[i]);
                    C = (M == nm ? C : 0) + (shf[i] == nm ? shi[i] : 0);
                    M = nm;
                }
                bm = M; bc = C;
            }
            __syncthreads();
            float m2 = bm; int c2 = bc;
            if (rank + c2 > samp) { ans = m2; break; }
            rank += c2;
            thr = m2;
            __syncthreads();
        }
        if (tid == 0) g_trip[j] = fmaxf(0.f, 0.2f + ans - row[lab]);
        return;
    }

    // ----------------- qdl half-pair partials -----------------
    {
        int q    = group * RPC + (idx - 36);   // 0..4095
        int pair = q >> 1;
        int half = q & 1;
        const float4* A = (const float4*)(qhd + (size_t)(2 * pair)     * DN + half * (DN / 2));
        const float4* B = (const float4*)(qhd + (size_t)(2 * pair + 1) * DN + half * (DN / 2));
        float sxx = 0.f, syy = 0.f, sxy = 0.f;
        #pragma unroll
        for (int i = 0; i < (DN / 8) / 256; i++) {
            int ii = tid + i * 256;
            float4 a = __ldcs(&A[ii]), b = __ldcs(&B[ii]);
            sxx += a.x * a.x + a.y * a.y + a.z * a.z + a.w * a.w;
            syy += b.x * b.x + b.y * b.y + b.z * b.z + b.w * b.w;
            sxy += a.x * b.x + a.y * b.y + a.z * b.z + a.w * b.w;
        }
        sxx = warpSum(sxx); syy = warpSum(syy); sxy = warpSum(sxy);
        __shared__ float sh[3][8];
        if (l == 0) { sh[0][w] = sxx; sh[1][w] = syy; sh[2][w] = sxy; }
        __syncthreads();
        if (tid == 0) {
            float X = 0.f, Y = 0.f, Z = 0.f;
            #pragma unroll
            for (int i = 0; i < 8; i++) { X += sh[0][i]; Y += sh[1][i]; Z += sh[2][i]; }
            float* dst = &g_qdlp[(size_t)q * 3];
            dst[0] = X; dst[1] = Y; dst[2] = Z;
        }
    }
}

// ===========================================================================
// Merge + final + reset. 32 blocks x 256. All reads dense & coalesced.
//   gid <  4096        : NCE t2v row + trip t2v pickup (pure loads)
//   4096 <= gid < 6144 : per-video column finalization (NCE v2t + trip v2t)
//   6144 <= gid < 8192 : QDL pair finalization
// ===========================================================================
__global__ void k_merge(float* __restrict__ out) {
    int gid = blockIdx.x * 256 + threadIdx.x;
    int l = threadIdx.x & 31;
    if (gid < QN) {
        int j = gid;
        float nce_val  = g_nceRow[j];
        float trip_val = g_trip[j];
        nce_val  = warpSum(nce_val);
        trip_val = warpSum(trip_val);
        if (l == 0) {
            atomicAdd(&g_bank[0][(j >> 5) & (NBANK - 1)], (double)nce_val);
            atomicAdd(&g_bank[2][(j >> 5) & (NBANK - 1)], (double)trip_val);
        }
    } else if (gid < QN + VN) {
        int v = gid - QN;
        float cs = g_colsum[v];
        float cm = funkey(g_colkey[v]);
        float a = g_diagS_[2 * v], b = g_diagS_[2 * v + 1];
        float nce_val = __logf(cs) - __logf(__expf(a) + __expf(b));
        float ta = g_diagS[2 * v], tb = g_diagS[2 * v + 1];
        float trip_val = fmaxf(0.f, 0.2f + cm - 0.5f * (ta + tb));
        nce_val  = warpSum(nce_val);
        trip_val = warpSum(trip_val);
        if (l == 0) {
            atomicAdd(&g_bank[1][(v >> 5) & (NBANK - 1)], (double)nce_val);
            atomicAdd(&g_bank[3][(v >> 5) & (NBANK - 1)], (double)trip_val);
        }
    } else if (gid < QN + 2 * VN) {
        int p = gid - QN - VN;
        const float* h0 = &g_qdlp[(size_t)(2 * p) * 3];
        const float* h1 = &g_qdlp[(size_t)(2 * p + 1) * 3];
        float X = h0[0] + h1[0], Y = h0[1] + h1[1], Z = h0[2] + h1[2];
        float nx = fmaxf(sqrtf(X), 1e-12f);
        float ny = fmaxf(sqrtf(Y), 1e-12f);
        float c  = Z / (nx * ny);
        float z  = 32.0f * (c + 0.1f);
        float sp = (z > 20.0f) ? z : log1pf(__expf(z));
        sp = warpSum(2.0f * sp);
        if (l == 0) atomicAdd(&g_bank[4][(p >> 5) & (NBANK - 1)], (double)sp);
    }

    // ---- last-block final combine + reset ----
    __threadfence();
    __shared__ int lastb;
    __syncthreads();
    if (threadIdx.x == 0) lastb = (atomicAdd(&g_done, 1u) == gridDim.x - 1);
    __syncthreads();
    if (!lastb) return;
    __threadfence();

    __shared__ double bsum[5];
    int wp = threadIdx.x >> 5;
    if (wp < 5) {
        double v = g_bank[wp][l] + g_bank[wp][l + 32];
        v = warpSumD(v);
        if (l == 0) bsum[wp] = v;
    }
    __syncthreads();
    if (threadIdx.x == 0) {
        double total = 0.02 * (bsum[0] / QN + bsum[1] / VN)
                     + (bsum[2] / QN + bsum[3] / VN)
                     + 0.04 * (bsum[4] / QN);
        out[0] = (float)total;
    }
    __syncthreads();   // read-out strictly before reset
    for (int i = threadIdx.x; i < 5 * NBANK; i += 256) ((double*)g_bank)[i] = 0.0;
    for (int i = threadIdx.x; i < VN; i += 256) { g_colsum[i] = 0.f; g_colkey[i] = 0u; }
    if (threadIdx.x == 0) g_done = 0u;
}

extern "C" void kernel_launch(void* const* d_in, const int* in_sizes, int n_in,
                              void* d_out, int out_size) {
    const float* scores   = (const float*)d_in[0];   // hd_similarity_scores  [Q,V]
    const float* scores_  = (const float*)d_in[1];   // hd_similarity_scores_ [Q,V]
    const float* qhd      = (const float*)d_in[2];   // query_hd [Q,D]
    const int*   rand_idx = (const int*)d_in[4];
    float* out = (float*)d_out;

    k_fused<<<NCHUNK * GRP, 256>>>(scores, scores_, qhd, rand_idx);
    k_merge<<<(QN + 2 * VN) / 256, 256>>>(out);
}